// round 14
// baseline (speedup 1.0000x reference)
#include <cuda_runtime.h>

#define PSSM_BATCH  2
#define PSSM_SEQ    2048
#define PSSM_DIN    128
#define PSSM_NST    64
#define PSSM_NC     64      // chunks per sequence
#define PSSM_CL     32      // chunk length
#define PSSM_LOG2E  1.4426950408889634f

// ---- scratch (static device arrays; no allocation) ----
__device__ float g_xc   [PSSM_BATCH*PSSM_DIN*PSSM_SEQ];            // (b,d,l)
__device__ float g_delta[PSSM_BATCH*PSSM_DIN*PSSM_SEQ];            // (b,d,l) sigmoid applied
__device__ float g_u    [PSSM_BATCH*PSSM_DIN*PSSM_SEQ];            // (b,d,l) delta*x_conv
__device__ float g_v    [PSSM_BATCH*PSSM_DIN*PSSM_SEQ];            // (b,d,l) x_conv
__device__ float g_B    [PSSM_BATCH*PSSM_SEQ*PSSM_NST];            // (b,l,n)
__device__ float g_C    [PSSM_BATCH*PSSM_SEQ*PSSM_NST];            // (b,l,n)
__device__ float g_a2   [PSSM_NST];                                // rowsum(A)*log2(e)
__device__ float g_hloc [PSSM_BATCH*2*PSSM_NC*PSSM_DIN*PSSM_NST];  // (b,dir,c,d,n)
__device__ float g_carry[PSSM_BATCH*2*PSSM_NC*PSSM_DIN*PSSM_NST];  // (b,dir,c,d,n)
__device__ float g_dS   [PSSM_BATCH*PSSM_NC*PSSM_DIN];             // (b,c,d)

// ============================================================
// Stage 1: projection xp = x @ W^T.  (unchanged from R12)
// grid (64, 12), block 256.
// ============================================================
__global__ void __launch_bounds__(256) pssm_proj_kernel(
    const float* __restrict__ x,
    const float* __restrict__ W,
    const float* __restrict__ A)
{
    __shared__ float xsT[64 * 65];
    __shared__ float Wsm[32 * 64];

    const int tid = threadIdx.x;
    const int og  = blockIdx.y;
    const int t0  = blockIdx.x * 64;

    if (blockIdx.x == 0 && blockIdx.y == 0 && tid < PSSM_NST) {
        float s = 0.f;
        const float* ar = A + tid * PSSM_NST;
        #pragma unroll 8
        for (int j = 0; j < PSSM_NST; j++) s += ar[j];
        g_a2[tid] = s * PSSM_LOG2E;
    }

    {
        const float4* wsrc = (const float4*)(W + og * 32 * 64);
        float4* wdst = (float4*)Wsm;
        wdst[tid]       = __ldg(&wsrc[tid]);
        wdst[tid + 256] = __ldg(&wsrc[tid + 256]);
    }

    #pragma unroll
    for (int i = 0; i < 4; i++) {
        const int f  = tid + 256 * i;
        const int t  = f >> 4;
        const int c4 = (f & 15) * 4;
        const float4 v = __ldg((const float4*)(x + (t0 + t) * 64 + c4));
        xsT[(c4 + 0) * 65 + t] = v.x;
        xsT[(c4 + 1) * 65 + t] = v.y;
        xsT[(c4 + 2) * 65 + t] = v.z;
        xsT[(c4 + 3) * 65 + t] = v.w;
    }
    __syncthreads();

    const int oc = tid >> 6;
    const int t  = tid & 63;
    const int token = t0 + t;
    const int b = token >> 11;
    const int l = token & 2047;

    float acc[8] = {0.f, 0.f, 0.f, 0.f, 0.f, 0.f, 0.f, 0.f};

    #pragma unroll 4
    for (int k4 = 0; k4 < 16; k4++) {
        const int k = k4 * 4;
        const float x0 = xsT[(k + 0) * 65 + t];
        const float x1 = xsT[(k + 1) * 65 + t];
        const float x2 = xsT[(k + 2) * 65 + t];
        const float x3 = xsT[(k + 3) * 65 + t];
        #pragma unroll
        for (int i = 0; i < 8; i++) {
            const float4 w4 = *(const float4*)&Wsm[(oc * 8 + i) * 64 + k];
            acc[i] = fmaf(w4.x, x0, acc[i]);
            acc[i] = fmaf(w4.y, x1, acc[i]);
            acc[i] = fmaf(w4.z, x2, acc[i]);
            acc[i] = fmaf(w4.w, x3, acc[i]);
        }
    }

    const int obase = og * 32 + oc * 8;
    if (obase < 128) {
        #pragma unroll
        for (int i = 0; i < 8; i++)
            g_xc[(b * PSSM_DIN + obase + i) * PSSM_SEQ + l] = acc[i];
    } else if (obase < 256) {
        #pragma unroll
        for (int i = 0; i < 8; i++)
            g_delta[(b * PSSM_DIN + (obase - 128 + i)) * PSSM_SEQ + l] =
                __fdividef(1.f, 1.f + __expf(-acc[i]));
    } else if (obase < 320) {
        float4* dst = (float4*)&g_B[(b * PSSM_SEQ + l) * PSSM_NST + (obase - 256)];
        dst[0] = make_float4(acc[0], acc[1], acc[2], acc[3]);
        dst[1] = make_float4(acc[4], acc[5], acc[6], acc[7]);
    } else {
        float4* dst = (float4*)&g_C[(b * PSSM_SEQ + l) * PSSM_NST + (obase - 320)];
        dst[0] = make_float4(acc[0], acc[1], acc[2], acc[3]);
        dst[1] = make_float4(acc[4], acc[5], acc[6], acc[7]);
    }
}

// ============================================================
// Phase A (conv fused, single fwd pass for BOTH dirs), CL=32.
// warp = d-pair; half-warp = one d; lane r holds states 4r..4r+3.
// grid 1024: blk = (b<<9)|(c<<3)|dg.  block 256 = 8 warps = 16 d.
// ============================================================
__global__ void __launch_bounds__(256) pssm_scanA_kernel(
    const float* __restrict__ cw, const float* __restrict__ cb)
{
    __shared__ float Bs[PSSM_CL * PSSM_NST];   // 8KB

    const int blk = blockIdx.x;
    const int dg  = blk & 7;
    const int c   = (blk >> 3) & 63;
    const int b   = blk >> 9;

    const int tid  = threadIdx.x;
    const int w    = tid >> 5;
    const int lane = tid & 31;
    const int half = lane >> 4;
    const int r    = lane & 15;
    const int d    = dg * 16 + w * 2 + half;

    {   // stage B chunk: 512 float4, 2/thread
        const float4* s4 = (const float4*)(g_B + (b * PSSM_SEQ + c * PSSM_CL) * PSSM_NST);
        float4* d4p = (float4*)Bs;
        #pragma unroll
        for (int i = 0; i < 2; i++)
            d4p[tid + 256 * i] = __ldg(&s4[tid + 256 * i]);
    }
    __syncthreads();

    const int off = (b * PSSM_DIN + d) * PSSM_SEQ + c * PSSM_CL;
    const float* dl  = g_delta + off;
    const float* xcl = g_xc + off;
    float* uw = g_u + off;
    float* vw = g_v + off;

    const float4 a4 = __ldg((const float4*)&g_a2[r * 4]);
    const float cw0 = __ldg(&cw[d * 4 + 0]);
    const float cw1 = __ldg(&cw[d * 4 + 1]);
    const float cw2 = __ldg(&cw[d * 4 + 2]);
    const float cw3 = __ldg(&cw[d * 4 + 3]);
    const float bias = __ldg(&cb[d]);

    float hf0 = 0.f, hf1 = 0.f, hf2 = 0.f, hf3 = 0.f;
    float bk0 = 0.f, bk1 = 0.f, bk2 = 0.f, bk3 = 0.f;
    float P0 = 1.f, P1 = 1.f, P2 = 1.f, P3 = 1.f;
    float ds = 0.f;

    float4 xp = (c == 0) ? make_float4(0.f, 0.f, 0.f, 0.f)
                         : __ldg((const float4*)(xcl - 4));
    float4 xq = __ldg((const float4*)(xcl));
    float4 d4 = __ldg((const float4*)(dl));

    #pragma unroll 2
    for (int s = 0; s < 8; s++) {
        const int lb = 4 * s;
        float4 xqn, d4n;
        if (s < 7) {
            xqn = __ldg((const float4*)(xcl + lb + 4));
            d4n = __ldg((const float4*)(dl + lb + 4));
        }

        float v0 = bias, v1 = bias, v2 = bias, v3 = bias;
        v0 = fmaf(cw0, xp.y, v0); v0 = fmaf(cw1, xp.z, v0);
        v0 = fmaf(cw2, xp.w, v0); v0 = fmaf(cw3, xq.x, v0);
        v1 = fmaf(cw0, xp.z, v1); v1 = fmaf(cw1, xp.w, v1);
        v1 = fmaf(cw2, xq.x, v1); v1 = fmaf(cw3, xq.y, v1);
        v2 = fmaf(cw0, xp.w, v2); v2 = fmaf(cw1, xq.x, v2);
        v2 = fmaf(cw2, xq.y, v2); v2 = fmaf(cw3, xq.z, v2);
        v3 = fmaf(cw0, xq.x, v3); v3 = fmaf(cw1, xq.y, v3);
        v3 = fmaf(cw2, xq.z, v3); v3 = fmaf(cw3, xq.w, v3);

        const float da[4] = {d4.x, d4.y, d4.z, d4.w};
        const float ua[4] = {da[0] * v0, da[1] * v1, da[2] * v2, da[3] * v3};

        if (r == 0) {
            *(float4*)(vw + lb) = make_float4(v0, v1, v2, v3);
            *(float4*)(uw + lb) = make_float4(ua[0], ua[1], ua[2], ua[3]);
        }

        #pragma unroll
        for (int k = 0; k < 4; k++) {
            const float e0 = exp2f(da[k] * a4.x);
            const float e1 = exp2f(da[k] * a4.y);
            const float e2 = exp2f(da[k] * a4.z);
            const float e3 = exp2f(da[k] * a4.w);
            const float4 B4 = *(const float4*)&Bs[(lb + k) * PSSM_NST + r * 4];
            const float t0 = ua[k] * B4.x;
            const float t1 = ua[k] * B4.y;
            const float t2 = ua[k] * B4.z;
            const float t3 = ua[k] * B4.w;
            bk0 = fmaf(t0, P0, bk0); bk1 = fmaf(t1, P1, bk1);
            bk2 = fmaf(t2, P2, bk2); bk3 = fmaf(t3, P3, bk3);
            hf0 = fmaf(e0, hf0, t0); hf1 = fmaf(e1, hf1, t1);
            hf2 = fmaf(e2, hf2, t2); hf3 = fmaf(e3, hf3, t3);
            P0 *= e0; P1 *= e1; P2 *= e2; P3 *= e3;
            ds += da[k];
        }

        xp = xq;
        if (s < 7) { xq = xqn; d4 = d4n; }
    }

    const int hstep = PSSM_NC * PSSM_DIN * PSSM_NST;
    float* hl = g_hloc + (((b * 2) * PSSM_NC + c) * PSSM_DIN + d) * PSSM_NST;
    *(float4*)(hl + r * 4)         = make_float4(hf0, hf1, hf2, hf3);
    *(float4*)(hl + hstep + r * 4) = make_float4(bk0, bk1, bk2, bk3);
    if (r == 0)
        g_dS[(b * PSSM_NC + c) * PSSM_DIN + d] = ds;
}

// ============================================================
// Phase B: carry scan, 64 chunks, 2 per lane (pair-combine then
// 32-lane Hillis-Steele on (E1,h1)∘(E2,h2)=(E1E2, E2h1+h2)).
// One warp per (b,dir,d,n).
// ============================================================
__global__ void __launch_bounds__(512) pssm_carry_kernel()
{
    const int wid  = (blockIdx.x * 512 + threadIdx.x) >> 5;  // 0..32767
    const int lane = threadIdx.x & 31;
    const int n    = wid & 63;
    const int d    = (wid >> 6) & 127;
    const int dir  = (wid >> 13) & 1;
    const int b    = wid >> 14;

    const float a2n = g_a2[n];
    const int i0 = 2 * lane, i1 = 2 * lane + 1;           // application order
    const int c0 = dir ? (63 - i0) : i0;
    const int c1 = dir ? (63 - i1) : i1;
    const int base = ((b * 2 + dir) * PSSM_NC) * PSSM_DIN * PSSM_NST
                   + d * PSSM_NST + n;
    const int dsb  = b * PSSM_NC * PSSM_DIN + d;
    const int o0 = base + c0 * PSSM_DIN * PSSM_NST;
    const int o1 = base + c1 * PSSM_DIN * PSSM_NST;

    const float h0 = g_hloc[o0];
    const float h1 = g_hloc[o1];
    const float E0 = exp2f(a2n * g_dS[dsb + c0 * PSSM_DIN]);
    const float E1 = exp2f(a2n * g_dS[dsb + c1 * PSSM_DIN]);

    float E = E0 * E1;
    float h = fmaf(E1, h0, h1);

    #pragma unroll
    for (int ofs = 1; ofs < 32; ofs <<= 1) {
        const float ph = __shfl_up_sync(0xffffffffu, h, ofs);
        const float pe = __shfl_up_sync(0xffffffffu, E, ofs);
        if (lane >= ofs) { h = fmaf(E, ph, h); E *= pe; }
    }
    float hex = __shfl_up_sync(0xffffffffu, h, 1);
    hex = (lane == 0) ? 0.f : hex;

    g_carry[o0] = hex;
    g_carry[o1] = fmaf(E0, hex, h0);
}

// ============================================================
// Phase C: register-state scan.  warp = 8 d x 1 dir; lane
// (dl8 = lane&7 -> d, sq = lane>>3 -> state-quarter) keeps
// h[16] states in regs.  B/C read via quarter-broadcast
// LDS.128 from pad-20 layout (4 distinct bank spans).
// delta/u/v staged in padded [32 d][33] smem tiles.
// Reduction: 2 shfl_xor + 1 STS.  Static smem 42KB.
// grid 512: blk = (b<<8)|(c<<2)|dq.  block 256 = 8 warps.
// ============================================================
__global__ void __launch_bounds__(256, 4) pssm_scanC_kernel(
    float* __restrict__ y, const float* __restrict__ Dp)
{
    __shared__ float Bsm [PSSM_CL * 80];       // [t][sq*20 + k], 10240B
    __shared__ float Csm [PSSM_CL * 80];
    __shared__ float dsm [32 * 33];            // [dloc][t]
    __shared__ float usm [32 * 33];
    __shared__ float vsm [32 * 33];
    __shared__ float ysum[PSSM_CL * 2 * 36];   // [t][dir][dloc]

    const int blk = blockIdx.x;
    const int dq  = blk & 3;                   // 32-d group
    const int c   = (blk >> 2) & 63;
    const int b   = blk >> 8;

    const int tid  = threadIdx.x;
    const int w    = tid >> 5;
    const int lane = tid & 31;
    const int dir  = w & 1;                    // warp-uniform
    const int dgrp = w >> 1;                   // 0..3, 8 d each
    const int dl8  = lane & 7;
    const int sq   = lane >> 3;                // state quarter
    const int dloc = dgrp * 8 + dl8;           // 0..31
    const int d    = dq * 32 + dloc;

    {   // stage B/C: 512 float4 each, pad-20 quarter layout
        const int gbase = (b * PSSM_SEQ + c * PSSM_CL) * PSSM_NST;
        const float4* sB = (const float4*)(g_B + gbase);
        const float4* sC = (const float4*)(g_C + gbase);
        #pragma unroll
        for (int i = 0; i < 2; i++) {
            const int f  = tid + 256 * i;      // float4 index 0..511
            const int l  = f >> 4;             // 0..31
            const int s4 = (f & 15) * 4;       // 0..60
            const int dst = l * 80 + s4 + (s4 >> 4) * 4;
            *(float4*)&Bsm[dst] = __ldg(&sB[f]);
            *(float4*)&Csm[dst] = __ldg(&sC[f]);
        }
    }
    {   // stage delta/u/v scalars: 1024 each, coalesced rows
        const int base_d = b * PSSM_DIN + dq * 32;
        #pragma unroll
        for (int i = 0; i < 4; i++) {
            const int f  = tid + 256 * i;      // 0..1023
            const int dd = f >> 5, t = f & 31;
            const int src = (base_d + dd) * PSSM_SEQ + c * PSSM_CL + t;
            dsm[dd * 33 + t] = g_delta[src];
            usm[dd * 33 + t] = g_u[src];
            vsm[dd * 33 + t] = g_v[src];
        }
    }
    __syncthreads();

    // register state: 16 states (sq's quarter) + their a2
    float a2r[16], h[16];
    {
        const float4* ap = (const float4*)&g_a2[sq * 16];
        const float* cr = g_carry
            + ((size_t)((b * 2 + dir) * PSSM_NC + c)) * (PSSM_DIN * PSSM_NST)
            + d * PSSM_NST + sq * 16;
        #pragma unroll
        for (int k4 = 0; k4 < 4; k4++) {
            const float4 av = __ldg(&ap[k4]);
            a2r[k4*4+0] = av.x; a2r[k4*4+1] = av.y;
            a2r[k4*4+2] = av.z; a2r[k4*4+3] = av.w;
            const float4 hv = *(const float4*)(cr + k4 * 4);
            h[k4*4+0] = hv.x; h[k4*4+1] = hv.y;
            h[k4*4+2] = hv.z; h[k4*4+3] = hv.w;
        }
    }

    const float* dsr = dsm + dloc * 33;
    const float* usr = usm + dloc * 33;
    const int qoff = sq * 20;

    #pragma unroll 4
    for (int s = 0; s < PSSM_CL; s++) {
        const int t = dir ? (PSSM_CL - 1 - s) : s;
        const float dj = dsr[t];
        const float uj = usr[t];
        const float* Brow = Bsm + t * 80 + qoff;
        const float* Crow = Csm + t * 80 + qoff;
        float p = 0.f;
        #pragma unroll
        for (int k4 = 0; k4 < 4; k4++) {
            const float4 B4 = *(const float4*)(Brow + k4 * 4);
            const float4 C4 = *(const float4*)(Crow + k4 * 4);
            float e;
            e = exp2f(dj * a2r[k4*4+0]); h[k4*4+0] = fmaf(e, h[k4*4+0], uj * B4.x); p = fmaf(h[k4*4+0], C4.x, p);
            e = exp2f(dj * a2r[k4*4+1]); h[k4*4+1] = fmaf(e, h[k4*4+1], uj * B4.y); p = fmaf(h[k4*4+1], C4.y, p);
            e = exp2f(dj * a2r[k4*4+2]); h[k4*4+2] = fmaf(e, h[k4*4+2], uj * B4.z); p = fmaf(h[k4*4+2], C4.z, p);
            e = exp2f(dj * a2r[k4*4+3]); h[k4*4+3] = fmaf(e, h[k4*4+3], uj * B4.w); p = fmaf(h[k4*4+3], C4.w, p);
        }
        p += __shfl_xor_sync(0xffffffffu, p, 8);
        p += __shfl_xor_sync(0xffffffffu, p, 16);
        if (sq == 0) ysum[(t * 2 + dir) * 36 + dloc] = p;
    }
    __syncthreads();

    // epilogue: 1024 cells = 32 l x 32 d, 4/thread, coalesced stores
    #pragma unroll
    for (int i = 0; i < 4; i++) {
        const int cell = tid + 256 * i;
        const int l  = cell >> 5;
        const int dd = cell & 31;
        const float val = ysum[(l * 2) * 36 + dd] + ysum[(l * 2 + 1) * 36 + dd]
                        + __ldg(&Dp[dq * 32 + dd]) * vsm[dd * 33 + l];
        y[(size_t)(b * PSSM_SEQ + c * PSSM_CL + l) * PSSM_DIN + dq * 32 + dd] = val;
    }
}

// ============================================================
extern "C" void kernel_launch(void* const* d_in, const int* in_sizes, int n_in,
                              void* d_out, int out_size)
{
    const float* x  = (const float*)d_in[0];
    const float* W  = (const float*)d_in[1];
    const float* cw = (const float*)d_in[2];
    const float* cb = (const float*)d_in[3];
    const float* A  = (const float*)d_in[4];
    const float* Dp = (const float*)d_in[5];
    float* y = (float*)d_out;

    dim3 pg(64, 12);
    pssm_proj_kernel<<<pg, 256>>>(x, W, A);
    pssm_scanA_kernel<<<1024, 256>>>(cw, cb);
    pssm_carry_kernel<<<2048, 512>>>();
    pssm_scanC_kernel<<<512, 256>>>(y, Dp);
}

// round 15
// speedup vs baseline: 1.1451x; 1.1451x over previous
#include <cuda_runtime.h>

#define PSSM_BATCH  2
#define PSSM_SEQ    2048
#define PSSM_DIN    128
#define PSSM_NST    64
#define PSSM_NC     32      // chunks per sequence
#define PSSM_CL     64      // chunk length
#define PSSM_LOG2E  1.4426950408889634f

// ---- scratch (static device arrays; no allocation) ----
__device__ float g_xc   [PSSM_BATCH*PSSM_DIN*PSSM_SEQ];            // (b,d,l)
__device__ float g_delta[PSSM_BATCH*PSSM_DIN*PSSM_SEQ];            // (b,d,l) sigmoid applied
__device__ float g_u    [PSSM_BATCH*PSSM_DIN*PSSM_SEQ];            // (b,d,l) delta*x_conv
__device__ float g_v    [PSSM_BATCH*PSSM_DIN*PSSM_SEQ];            // (b,d,l) x_conv
__device__ float g_B    [PSSM_BATCH*PSSM_SEQ*PSSM_NST];            // (b,l,n)
__device__ float g_C    [PSSM_BATCH*PSSM_SEQ*PSSM_NST];            // (b,l,n)
__device__ float g_a2   [PSSM_NST];                                // rowsum(A)*log2(e)
__device__ float g_hloc [PSSM_BATCH*2*PSSM_NC*PSSM_DIN*PSSM_NST];  // (b,dir,c,d,n)
__device__ float g_carry[PSSM_BATCH*2*PSSM_NC*PSSM_DIN*PSSM_NST];  // (b,dir,c,d,n)
__device__ float g_dS   [PSSM_BATCH*PSSM_NC*PSSM_DIN];             // (b,c,d)

// scanC dynamic smem layout (floats) -- 8-row tile for 3 blocks/SM
#define SMC_B     0                       // 4096
#define SMC_C     4096                    // 4096
#define SMC_TILE  8192                    // 16 warps x (8 x 36) = 4608
#define SMC_YSUM  12800                   // 64 x 33 = 2112
#define SMC_VS    14912                   // 16 x 65 = 1040
#define SMC_TOTAL_BYTES (15952 * 4)       // 63808 B

// ============================================================
// Stage 1: projection xp = x @ W^T.
// grid (64, 12), block 256.  bx -> 64-token tile, by -> 32 outputs.
// ============================================================
__global__ void __launch_bounds__(256) pssm_proj_kernel(
    const float* __restrict__ x,
    const float* __restrict__ W,
    const float* __restrict__ A)
{
    __shared__ float xsT[64 * 65];    // [k][t], pad 65  (16.6KB)
    __shared__ float Wsm[32 * 64];    // [i][k]          (8KB)

    const int tid = threadIdx.x;
    const int og  = blockIdx.y;                  // 0..11
    const int t0  = blockIdx.x * 64;             // global token base

    if (blockIdx.x == 0 && blockIdx.y == 0 && tid < PSSM_NST) {
        float s = 0.f;
        const float* ar = A + tid * PSSM_NST;
        #pragma unroll 8
        for (int j = 0; j < PSSM_NST; j++) s += ar[j];
        g_a2[tid] = s * PSSM_LOG2E;
    }

    {
        const float4* wsrc = (const float4*)(W + og * 32 * 64);
        float4* wdst = (float4*)Wsm;
        wdst[tid]       = __ldg(&wsrc[tid]);
        wdst[tid + 256] = __ldg(&wsrc[tid + 256]);
    }

    #pragma unroll
    for (int i = 0; i < 4; i++) {
        const int f  = tid + 256 * i;
        const int t  = f >> 4;
        const int c4 = (f & 15) * 4;
        const float4 v = __ldg((const float4*)(x + (t0 + t) * 64 + c4));
        xsT[(c4 + 0) * 65 + t] = v.x;
        xsT[(c4 + 1) * 65 + t] = v.y;
        xsT[(c4 + 2) * 65 + t] = v.z;
        xsT[(c4 + 3) * 65 + t] = v.w;
    }
    __syncthreads();

    const int oc = tid >> 6;          // 0..3
    const int t  = tid & 63;
    const int token = t0 + t;
    const int b = token >> 11;
    const int l = token & 2047;

    float acc[8] = {0.f, 0.f, 0.f, 0.f, 0.f, 0.f, 0.f, 0.f};

    #pragma unroll 4
    for (int k4 = 0; k4 < 16; k4++) {
        const int k = k4 * 4;
        const float x0 = xsT[(k + 0) * 65 + t];
        const float x1 = xsT[(k + 1) * 65 + t];
        const float x2 = xsT[(k + 2) * 65 + t];
        const float x3 = xsT[(k + 3) * 65 + t];
        #pragma unroll
        for (int i = 0; i < 8; i++) {
            const float4 w4 = *(const float4*)&Wsm[(oc * 8 + i) * 64 + k];
            acc[i] = fmaf(w4.x, x0, acc[i]);
            acc[i] = fmaf(w4.y, x1, acc[i]);
            acc[i] = fmaf(w4.z, x2, acc[i]);
            acc[i] = fmaf(w4.w, x3, acc[i]);
        }
    }

    const int obase = og * 32 + oc * 8;          // block-uniform segment
    if (obase < 128) {
        #pragma unroll
        for (int i = 0; i < 8; i++)
            g_xc[(b * PSSM_DIN + obase + i) * PSSM_SEQ + l] = acc[i];
    } else if (obase < 256) {
        #pragma unroll
        for (int i = 0; i < 8; i++)
            g_delta[(b * PSSM_DIN + (obase - 128 + i)) * PSSM_SEQ + l] =
                __fdividef(1.f, 1.f + __expf(-acc[i]));
    } else if (obase < 320) {
        float4* dst = (float4*)&g_B[(b * PSSM_SEQ + l) * PSSM_NST + (obase - 256)];
        dst[0] = make_float4(acc[0], acc[1], acc[2], acc[3]);
        dst[1] = make_float4(acc[4], acc[5], acc[6], acc[7]);
    } else {
        float4* dst = (float4*)&g_C[(b * PSSM_SEQ + l) * PSSM_NST + (obase - 320)];
        dst[0] = make_float4(acc[0], acc[1], acc[2], acc[3]);
        dst[1] = make_float4(acc[4], acc[5], acc[6], acc[7]);
    }
}

// ============================================================
// Phase A (conv fused, single forward pass for BOTH dirs), CL=64.
// warp = d-pair; half-warp = one d; lane r holds states 4r..4r+3.
// grid 512: blk = (b<<8)|(c<<3)|dg.  block 256 = 8 warps = 16 d.
// ============================================================
__global__ void __launch_bounds__(256) pssm_scanA_kernel(
    const float* __restrict__ cw, const float* __restrict__ cb)
{
    __shared__ float Bs[PSSM_CL * PSSM_NST];   // 16KB

    const int blk = blockIdx.x;
    const int dg  = blk & 7;              // 8 groups of 16 d
    const int c   = (blk >> 3) & 31;
    const int b   = blk >> 8;

    const int tid  = threadIdx.x;
    const int w    = tid >> 5;            // 0..7 d-pair
    const int lane = tid & 31;
    const int half = lane >> 4;
    const int r    = lane & 15;
    const int d    = dg * 16 + w * 2 + half;

    {   // stage B chunk: 1024 float4, 4/thread
        const float4* s4 = (const float4*)(g_B + (b * PSSM_SEQ + c * PSSM_CL) * PSSM_NST);
        float4* d4p = (float4*)Bs;
        #pragma unroll
        for (int i = 0; i < 4; i++)
            d4p[tid + 256 * i] = __ldg(&s4[tid + 256 * i]);
    }
    __syncthreads();

    const int off = (b * PSSM_DIN + d) * PSSM_SEQ + c * PSSM_CL;
    const float* dl  = g_delta + off;
    const float* xcl = g_xc + off;
    float* uw = g_u + off;
    float* vw = g_v + off;

    const float4 a4 = __ldg((const float4*)&g_a2[r * 4]);
    const float cw0 = __ldg(&cw[d * 4 + 0]);
    const float cw1 = __ldg(&cw[d * 4 + 1]);
    const float cw2 = __ldg(&cw[d * 4 + 2]);
    const float cw3 = __ldg(&cw[d * 4 + 3]);
    const float bias = __ldg(&cb[d]);

    float hf0 = 0.f, hf1 = 0.f, hf2 = 0.f, hf3 = 0.f;    // fwd end-state
    float bk0 = 0.f, bk1 = 0.f, bk2 = 0.f, bk3 = 0.f;    // bwd end-state
    float P0 = 1.f, P1 = 1.f, P2 = 1.f, P3 = 1.f;        // prefix product
    float ds = 0.f;

    // prefetch pipeline: xp(s) == xq(s-1)
    float4 xp = (c == 0) ? make_float4(0.f, 0.f, 0.f, 0.f)
                         : __ldg((const float4*)(xcl - 4));
    float4 xq = __ldg((const float4*)(xcl));
    float4 d4 = __ldg((const float4*)(dl));

    #pragma unroll 4
    for (int s = 0; s < 16; s++) {
        const int lb = 4 * s;
        float4 xqn, d4n;
        if (s < 15) {
            xqn = __ldg((const float4*)(xcl + lb + 4));
            d4n = __ldg((const float4*)(dl + lb + 4));
        }

        // depthwise conv k=4 (cw0..cw3 hit x[l-3..l])
        float v0 = bias, v1 = bias, v2 = bias, v3 = bias;
        v0 = fmaf(cw0, xp.y, v0); v0 = fmaf(cw1, xp.z, v0);
        v0 = fmaf(cw2, xp.w, v0); v0 = fmaf(cw3, xq.x, v0);
        v1 = fmaf(cw0, xp.z, v1); v1 = fmaf(cw1, xp.w, v1);
        v1 = fmaf(cw2, xq.x, v1); v1 = fmaf(cw3, xq.y, v1);
        v2 = fmaf(cw0, xp.w, v2); v2 = fmaf(cw1, xq.x, v2);
        v2 = fmaf(cw2, xq.y, v2); v2 = fmaf(cw3, xq.z, v2);
        v3 = fmaf(cw0, xq.x, v3); v3 = fmaf(cw1, xq.y, v3);
        v3 = fmaf(cw2, xq.z, v3); v3 = fmaf(cw3, xq.w, v3);

        const float da[4] = {d4.x, d4.y, d4.z, d4.w};
        const float ua[4] = {da[0] * v0, da[1] * v1, da[2] * v2, da[3] * v3};

        if (r == 0) {      // one writer per d per 4-elem group
            *(float4*)(vw + lb) = make_float4(v0, v1, v2, v3);
            *(float4*)(uw + lb) = make_float4(ua[0], ua[1], ua[2], ua[3]);
        }

        #pragma unroll
        for (int k = 0; k < 4; k++) {
            const float e0 = exp2f(da[k] * a4.x);
            const float e1 = exp2f(da[k] * a4.y);
            const float e2 = exp2f(da[k] * a4.z);
            const float e3 = exp2f(da[k] * a4.w);
            const float4 B4 = *(const float4*)&Bs[(lb + k) * PSSM_NST + r * 4];
            const float t0 = ua[k] * B4.x;
            const float t1 = ua[k] * B4.y;
            const float t2 = ua[k] * B4.z;
            const float t3 = ua[k] * B4.w;
            bk0 = fmaf(t0, P0, bk0); bk1 = fmaf(t1, P1, bk1);   // uses P BEFORE update
            bk2 = fmaf(t2, P2, bk2); bk3 = fmaf(t3, P3, bk3);
            hf0 = fmaf(e0, hf0, t0); hf1 = fmaf(e1, hf1, t1);
            hf2 = fmaf(e2, hf2, t2); hf3 = fmaf(e3, hf3, t3);
            P0 *= e0; P1 *= e1; P2 *= e2; P3 *= e3;
            ds += da[k];
        }

        xp = xq;
        if (s < 15) { xq = xqn; d4 = d4n; }
    }

    const int hstep = PSSM_NC * PSSM_DIN * PSSM_NST;      // dir stride
    float* hl = g_hloc + (((b * 2) * PSSM_NC + c) * PSSM_DIN + d) * PSSM_NST;
    *(float4*)(hl + r * 4)         = make_float4(hf0, hf1, hf2, hf3);   // dir 0
    *(float4*)(hl + hstep + r * 4) = make_float4(bk0, bk1, bk2, bk3);   // dir 1
    if (r == 0)
        g_dS[(b * PSSM_NC + c) * PSSM_DIN + d] = ds;
}

// ============================================================
// Phase B: warp-parallel carry scan.  One warp per (b,dir,d,n);
// lane <-> chunk (reversed for bwd).  Hillis-Steele on
// (E1,h1)∘(E2,h2) = (E1E2, E2h1+h2).
// ============================================================
__global__ void __launch_bounds__(512) pssm_carry_kernel()
{
    const int wid  = (blockIdx.x * 512 + threadIdx.x) >> 5;  // 0..32767
    const int lane = threadIdx.x & 31;
    const int n    = wid & 63;
    const int d    = (wid >> 6) & 127;
    const int dir  = (wid >> 13) & 1;
    const int b    = wid >> 14;

    const int c = dir ? (31 - lane) : lane;
    const float a2n = g_a2[n];
    const int o = ((b * 2 + dir) * PSSM_NC + c) * PSSM_DIN * PSSM_NST
                + d * PSSM_NST + n;

    float h = g_hloc[o];
    float E = exp2f(a2n * g_dS[(b * PSSM_NC + c) * PSSM_DIN + d]);

    #pragma unroll
    for (int ofs = 1; ofs < 32; ofs <<= 1) {
        const float ph = __shfl_up_sync(0xffffffffu, h, ofs);
        const float pe = __shfl_up_sync(0xffffffffu, E, ofs);
        if (lane >= ofs) { h = fmaf(E, ph, h); E *= pe; }
    }
    const float ex = __shfl_up_sync(0xffffffffu, h, 1);
    g_carry[o] = (lane == 0) ? 0.f : ex;
}

// ============================================================
// Phase C body (R9-proven layout, 8-row tile, no prefetch):
// warp = (d-pair, dir); half-warp = one d; lane r holds states
// 4r..4r+3.  Per-ts partial to warp tile (8 x 36); flush every
// 8 ts: lane sums 8 cols (2 LDS.128) + shfl_xor(8) combine,
// 16 writer lanes (r<8 per half).
// ============================================================
template<bool REV>
__device__ __forceinline__ void pssm_scanC_body(
    const float* __restrict__ dl, const float* __restrict__ ul,
    const float* __restrict__ Bsm, const float* __restrict__ Csm,
    float* __restrict__ tile, float* __restrict__ ysum,
    const float4 a4, const float4 hc,
    const int half, const int r, const int ycol)
{
    float h0 = hc.x, h1 = hc.y, h2 = hc.z, h3 = hc.w;
    const int wcol = half * 16 + r;

    #pragma unroll
    for (int grp = 0; grp < 8; grp++) {
        #pragma unroll
        for (int si = 0; si < 2; si++) {
            const int s  = grp * 2 + si;
            const int lb = REV ? (60 - 4 * s) : (4 * s);
            const float4 d4 = __ldg((const float4*)(dl + lb));
            const float4 u4 = __ldg((const float4*)(ul + lb));
            const float da[4] = {d4.x, d4.y, d4.z, d4.w};
            const float ua[4] = {u4.x, u4.y, u4.z, u4.w};
            #pragma unroll
            for (int k = 0; k < 4; k++) {
                const int j = REV ? (3 - k) : k;      // compile-time
                const int l = lb + j;
                const float e0 = exp2f(da[j] * a4.x);
                const float e1 = exp2f(da[j] * a4.y);
                const float e2 = exp2f(da[j] * a4.z);
                const float e3 = exp2f(da[j] * a4.w);
                const float4 B4 = *(const float4*)&Bsm[l * PSSM_NST + r * 4];
                const float4 C4 = *(const float4*)&Csm[l * PSSM_NST + r * 4];
                h0 = fmaf(e0, h0, ua[j] * B4.x);
                h1 = fmaf(e1, h1, ua[j] * B4.y);
                h2 = fmaf(e2, h2, ua[j] * B4.z);
                h3 = fmaf(e3, h3, ua[j] * B4.w);
                float p = h0 * C4.x;
                p = fmaf(h1, C4.y, p);
                p = fmaf(h2, C4.z, p);
                p = fmaf(h3, C4.w, p);
                tile[(l & 7) * 36 + wcol] = p;        // consecutive lanes, no conflict
            }
        }
        __syncwarp();
        // readback: lane (half, r) sums row (r&7), col-half (r>>3) of its half
        {
            const int row = r & 7;
            const int cb  = half * 16 + (r >> 3) * 8;
            const float4 v0 = *(const float4*)&tile[row * 36 + cb + 0];
            const float4 v1 = *(const float4*)&tile[row * 36 + cb + 4];
            float p = ((v0.x + v0.y) + (v0.z + v0.w))
                    + ((v1.x + v1.y) + (v1.z + v1.w));
            p += __shfl_xor_sync(0xffffffffu, p, 8);  // combine the two col-halves
            const int lg = REV ? (56 - 8 * grp) : (8 * grp);
            if (r < 8) ysum[(lg + row) * 33 + ycol] = p;
        }
        __syncwarp();   // protect tile before next group's writes
    }
}

// grid 512: blk = (b<<8)|(c<<3)|dg.  block 512 = 16 warps:
//   warp w: dir = w&1 (uniform), d-pair = w>>1; half-warp = one d.
// __launch_bounds__(512, 3): 3 blocks/SM target (regs <= 42).
__global__ void __launch_bounds__(512, 3) pssm_scanC_kernel(float* __restrict__ y,
                                                            const float* __restrict__ Dp)
{
    extern __shared__ float smC[];
    float* Bsm  = smC + SMC_B;
    float* Csm  = smC + SMC_C;
    float* tile = smC + SMC_TILE;
    float* ysum = smC + SMC_YSUM;
    float* vs   = smC + SMC_VS;

    const int blk = blockIdx.x;
    const int dg  = blk & 7;
    const int c   = (blk >> 3) & 31;
    const int b   = blk >> 8;

    const int tid  = threadIdx.x;
    const int w    = tid >> 5;
    const int lane = tid & 31;
    const int dir  = w & 1;               // warp-uniform
    const int pr   = w >> 1;              // d-pair 0..7
    const int half = lane >> 4;
    const int r    = lane & 15;
    const int dloc = pr * 2 + half;
    const int d    = dg * 16 + dloc;

    {   // stage B and C: 1024 float4 each, 2+2 per thread
        const int gbase = (b * PSSM_SEQ + c * PSSM_CL) * PSSM_NST;
        const float4* sB = (const float4*)(g_B + gbase);
        const float4* sC = (const float4*)(g_C + gbase);
        float4* dB = (float4*)Bsm;
        float4* dC = (float4*)Csm;
        #pragma unroll
        for (int i = 0; i < 2; i++) {
            dB[tid + 512 * i] = __ldg(&sB[tid + 512 * i]);
            dC[tid + 512 * i] = __ldg(&sC[tid + 512 * i]);
        }
    }
    #pragma unroll
    for (int i = 0; i < 2; i++) {
        const int e  = tid + 512 * i;
        const int dd = e >> 6, lv = e & 63;
        vs[dd * 65 + lv] =
            g_v[(b * PSSM_DIN + dg * 16 + dd) * PSSM_SEQ + c * PSSM_CL + lv];
    }
    __syncthreads();

    const int off = (b * PSSM_DIN + d) * PSSM_SEQ + c * PSSM_CL;
    const float* dl = g_delta + off;
    const float* ul = g_u + off;
    const float4 a4 = __ldg((const float4*)&g_a2[r * 4]);

    const float* cr = g_carry +
        ((((b * 2 + dir) * PSSM_NC + c) * PSSM_DIN + d) * PSSM_NST);
    const float4 hc = *(const float4*)(cr + r * 4);

    float* wtile = tile + w * 288;                 // 8 x 36 floats
    const int ycol = dloc * 2 + dir;

    if (dir == 0)
        pssm_scanC_body<false>(dl, ul, Bsm, Csm, wtile, ysum, a4, hc, half, r, ycol);
    else
        pssm_scanC_body<true >(dl, ul, Bsm, Csm, wtile, ysum, a4, hc, half, r, ycol);
    __syncthreads();

    // output: 1024 cells = 64 l x 16 d, 2 per thread, coalesced stores
    #pragma unroll
    for (int i = 0; i < 2; i++) {
        const int cell = tid + 512 * i;
        const int l  = cell >> 4;
        const int dd = cell & 15;
        const int dglob = dg * 16 + dd;
        const float val = ysum[l * 33 + dd * 2] + ysum[l * 33 + dd * 2 + 1]
                        + __ldg(&Dp[dglob]) * vs[dd * 65 + l];
        y[(size_t)(b * PSSM_SEQ + c * PSSM_CL + l) * PSSM_DIN + dglob] = val;
    }
}

// ============================================================
extern "C" void kernel_launch(void* const* d_in, const int* in_sizes, int n_in,
                              void* d_out, int out_size)
{
    const float* x  = (const float*)d_in[0];
    const float* W  = (const float*)d_in[1];
    const float* cw = (const float*)d_in[2];
    const float* cb = (const float*)d_in[3];
    const float* A  = (const float*)d_in[4];
    const float* Dp = (const float*)d_in[5];
    float* y = (float*)d_out;

    // opt-in to >48KB dynamic smem (idempotent; no allocation)
    static int smem_attr_set = 0;
    if (!smem_attr_set) {
        cudaFuncSetAttribute(pssm_scanC_kernel,
                             cudaFuncAttributeMaxDynamicSharedMemorySize,
                             SMC_TOTAL_BYTES);
        smem_attr_set = 1;
    }

    dim3 pg(64, 12);
    pssm_proj_kernel<<<pg, 256>>>(x, W, A);
    pssm_scanA_kernel<<<512, 256>>>(cw, cb);
    pssm_carry_kernel<<<2048, 512>>>();
    pssm_scanC_kernel<<<512, 512, SMC_TOTAL_BYTES>>>(y, Dp);
}

// round 16
// speedup vs baseline: 1.1813x; 1.0316x over previous
#include <cuda_runtime.h>

#define PSSM_BATCH  2
#define PSSM_SEQ    2048
#define PSSM_DIN    128
#define PSSM_NST    64
#define PSSM_NC     32      // chunks per sequence
#define PSSM_CL     64      // chunk length
#define PSSM_LOG2E  1.4426950408889634f

// ---- scratch (static device arrays; no allocation) ----
__device__ float g_xc   [PSSM_BATCH*PSSM_DIN*PSSM_SEQ];            // (b,d,l)
__device__ float g_delta[PSSM_BATCH*PSSM_DIN*PSSM_SEQ];            // (b,d,l) sigmoid applied
__device__ float g_u    [PSSM_BATCH*PSSM_DIN*PSSM_SEQ];            // (b,d,l) delta*x_conv
__device__ float g_v    [PSSM_BATCH*PSSM_DIN*PSSM_SEQ];            // (b,d,l) x_conv
__device__ float g_B    [PSSM_BATCH*PSSM_SEQ*PSSM_NST];            // (b,l,n)
__device__ float g_C    [PSSM_BATCH*PSSM_SEQ*PSSM_NST];            // (b,l,n)
__device__ float g_a2   [PSSM_NST];                                // rowsum(A)*log2(e)
__device__ float g_hloc [PSSM_BATCH*2*PSSM_NC*PSSM_DIN*PSSM_NST];  // (b,dir,c,d,n)
__device__ float g_carry[PSSM_BATCH*2*PSSM_NC*PSSM_DIN*PSSM_NST];  // (b,dir,c,d,n)
__device__ float g_dS   [PSSM_BATCH*PSSM_NC*PSSM_DIN];             // (b,c,d)

// scanC dynamic smem layout (floats)
#define SMC_B     0                       // 64*64 = 4096
#define SMC_C     4096                    // 4096
#define SMC_TILE  8192                    // 16 warps x 2 tiles x (8 x 36) = 9216
#define SMC_YSUM  17408                   // 64 x 67 = 4288
#define SMC_VS    21696                   // 32 x 65 = 2080
#define SMC_TOTAL_FLOATS 23776
#define SMC_TOTAL_BYTES (SMC_TOTAL_FLOATS * 4)   // 95104 B

// ============================================================
// Stage 1: projection xp = x @ W^T.
// grid (64, 12), block 256.
// ============================================================
__global__ void __launch_bounds__(256) pssm_proj_kernel(
    const float* __restrict__ x,
    const float* __restrict__ W,
    const float* __restrict__ A)
{
    __shared__ float xsT[64 * 65];
    __shared__ float Wsm[32 * 64];

    const int tid = threadIdx.x;
    const int og  = blockIdx.y;
    const int t0  = blockIdx.x * 64;

    if (blockIdx.x == 0 && blockIdx.y == 0 && tid < PSSM_NST) {
        float s = 0.f;
        const float* ar = A + tid * PSSM_NST;
        #pragma unroll 8
        for (int j = 0; j < PSSM_NST; j++) s += ar[j];
        g_a2[tid] = s * PSSM_LOG2E;
    }

    {
        const float4* wsrc = (const float4*)(W + og * 32 * 64);
        float4* wdst = (float4*)Wsm;
        wdst[tid]       = __ldg(&wsrc[tid]);
        wdst[tid + 256] = __ldg(&wsrc[tid + 256]);
    }

    #pragma unroll
    for (int i = 0; i < 4; i++) {
        const int f  = tid + 256 * i;
        const int t  = f >> 4;
        const int c4 = (f & 15) * 4;
        const float4 v = __ldg((const float4*)(x + (t0 + t) * 64 + c4));
        xsT[(c4 + 0) * 65 + t] = v.x;
        xsT[(c4 + 1) * 65 + t] = v.y;
        xsT[(c4 + 2) * 65 + t] = v.z;
        xsT[(c4 + 3) * 65 + t] = v.w;
    }
    __syncthreads();

    const int oc = tid >> 6;
    const int t  = tid & 63;
    const int token = t0 + t;
    const int b = token >> 11;
    const int l = token & 2047;

    float acc[8] = {0.f, 0.f, 0.f, 0.f, 0.f, 0.f, 0.f, 0.f};

    #pragma unroll 4
    for (int k4 = 0; k4 < 16; k4++) {
        const int k = k4 * 4;
        const float x0 = xsT[(k + 0) * 65 + t];
        const float x1 = xsT[(k + 1) * 65 + t];
        const float x2 = xsT[(k + 2) * 65 + t];
        const float x3 = xsT[(k + 3) * 65 + t];
        #pragma unroll
        for (int i = 0; i < 8; i++) {
            const float4 w4 = *(const float4*)&Wsm[(oc * 8 + i) * 64 + k];
            acc[i] = fmaf(w4.x, x0, acc[i]);
            acc[i] = fmaf(w4.y, x1, acc[i]);
            acc[i] = fmaf(w4.z, x2, acc[i]);
            acc[i] = fmaf(w4.w, x3, acc[i]);
        }
    }

    const int obase = og * 32 + oc * 8;
    if (obase < 128) {
        #pragma unroll
        for (int i = 0; i < 8; i++)
            g_xc[(b * PSSM_DIN + obase + i) * PSSM_SEQ + l] = acc[i];
    } else if (obase < 256) {
        #pragma unroll
        for (int i = 0; i < 8; i++)
            g_delta[(b * PSSM_DIN + (obase - 128 + i)) * PSSM_SEQ + l] =
                __fdividef(1.f, 1.f + __expf(-acc[i]));
    } else if (obase < 320) {
        float4* dst = (float4*)&g_B[(b * PSSM_SEQ + l) * PSSM_NST + (obase - 256)];
        dst[0] = make_float4(acc[0], acc[1], acc[2], acc[3]);
        dst[1] = make_float4(acc[4], acc[5], acc[6], acc[7]);
    } else {
        float4* dst = (float4*)&g_C[(b * PSSM_SEQ + l) * PSSM_NST + (obase - 320)];
        dst[0] = make_float4(acc[0], acc[1], acc[2], acc[3]);
        dst[1] = make_float4(acc[4], acc[5], acc[6], acc[7]);
    }
}

// ============================================================
// Phase A (conv fused, single forward pass for BOTH dirs), CL=64.
// warp = d-pair; half-warp = one d; lane r holds states 4r..4r+3.
// grid 512: blk = (b<<8)|(c<<3)|dg.  block 256 = 8 warps = 16 d.
// ============================================================
__global__ void __launch_bounds__(256) pssm_scanA_kernel(
    const float* __restrict__ cw, const float* __restrict__ cb)
{
    __shared__ float Bs[PSSM_CL * PSSM_NST];   // 16KB

    const int blk = blockIdx.x;
    const int dg  = blk & 7;
    const int c   = (blk >> 3) & 31;
    const int b   = blk >> 8;

    const int tid  = threadIdx.x;
    const int w    = tid >> 5;
    const int lane = tid & 31;
    const int half = lane >> 4;
    const int r    = lane & 15;
    const int d    = dg * 16 + w * 2 + half;

    {
        const float4* s4 = (const float4*)(g_B + (b * PSSM_SEQ + c * PSSM_CL) * PSSM_NST);
        float4* d4p = (float4*)Bs;
        #pragma unroll
        for (int i = 0; i < 4; i++)
            d4p[tid + 256 * i] = __ldg(&s4[tid + 256 * i]);
    }
    __syncthreads();

    const int off = (b * PSSM_DIN + d) * PSSM_SEQ + c * PSSM_CL;
    const float* dl  = g_delta + off;
    const float* xcl = g_xc + off;
    float* uw = g_u + off;
    float* vw = g_v + off;

    const float4 a4 = __ldg((const float4*)&g_a2[r * 4]);
    const float cw0 = __ldg(&cw[d * 4 + 0]);
    const float cw1 = __ldg(&cw[d * 4 + 1]);
    const float cw2 = __ldg(&cw[d * 4 + 2]);
    const float cw3 = __ldg(&cw[d * 4 + 3]);
    const float bias = __ldg(&cb[d]);

    float hf0 = 0.f, hf1 = 0.f, hf2 = 0.f, hf3 = 0.f;
    float bk0 = 0.f, bk1 = 0.f, bk2 = 0.f, bk3 = 0.f;
    float P0 = 1.f, P1 = 1.f, P2 = 1.f, P3 = 1.f;
    float ds = 0.f;

    float4 xp = (c == 0) ? make_float4(0.f, 0.f, 0.f, 0.f)
                         : __ldg((const float4*)(xcl - 4));
    float4 xq = __ldg((const float4*)(xcl));
    float4 d4 = __ldg((const float4*)(dl));

    #pragma unroll 4
    for (int s = 0; s < 16; s++) {
        const int lb = 4 * s;
        float4 xqn, d4n;
        if (s < 15) {
            xqn = __ldg((const float4*)(xcl + lb + 4));
            d4n = __ldg((const float4*)(dl + lb + 4));
        }

        float v0 = bias, v1 = bias, v2 = bias, v3 = bias;
        v0 = fmaf(cw0, xp.y, v0); v0 = fmaf(cw1, xp.z, v0);
        v0 = fmaf(cw2, xp.w, v0); v0 = fmaf(cw3, xq.x, v0);
        v1 = fmaf(cw0, xp.z, v1); v1 = fmaf(cw1, xp.w, v1);
        v1 = fmaf(cw2, xq.x, v1); v1 = fmaf(cw3, xq.y, v1);
        v2 = fmaf(cw0, xp.w, v2); v2 = fmaf(cw1, xq.x, v2);
        v2 = fmaf(cw2, xq.y, v2); v2 = fmaf(cw3, xq.z, v2);
        v3 = fmaf(cw0, xq.x, v3); v3 = fmaf(cw1, xq.y, v3);
        v3 = fmaf(cw2, xq.z, v3); v3 = fmaf(cw3, xq.w, v3);

        const float da[4] = {d4.x, d4.y, d4.z, d4.w};
        const float ua[4] = {da[0] * v0, da[1] * v1, da[2] * v2, da[3] * v3};

        if (r == 0) {
            *(float4*)(vw + lb) = make_float4(v0, v1, v2, v3);
            *(float4*)(uw + lb) = make_float4(ua[0], ua[1], ua[2], ua[3]);
        }

        #pragma unroll
        for (int k = 0; k < 4; k++) {
            const float e0 = exp2f(da[k] * a4.x);
            const float e1 = exp2f(da[k] * a4.y);
            const float e2 = exp2f(da[k] * a4.z);
            const float e3 = exp2f(da[k] * a4.w);
            const float4 B4 = *(const float4*)&Bs[(lb + k) * PSSM_NST + r * 4];
            const float t0 = ua[k] * B4.x;
            const float t1 = ua[k] * B4.y;
            const float t2 = ua[k] * B4.z;
            const float t3 = ua[k] * B4.w;
            bk0 = fmaf(t0, P0, bk0); bk1 = fmaf(t1, P1, bk1);
            bk2 = fmaf(t2, P2, bk2); bk3 = fmaf(t3, P3, bk3);
            hf0 = fmaf(e0, hf0, t0); hf1 = fmaf(e1, hf1, t1);
            hf2 = fmaf(e2, hf2, t2); hf3 = fmaf(e3, hf3, t3);
            P0 *= e0; P1 *= e1; P2 *= e2; P3 *= e3;
            ds += da[k];
        }

        xp = xq;
        if (s < 15) { xq = xqn; d4 = d4n; }
    }

    const int hstep = PSSM_NC * PSSM_DIN * PSSM_NST;
    float* hl = g_hloc + (((b * 2) * PSSM_NC + c) * PSSM_DIN + d) * PSSM_NST;
    *(float4*)(hl + r * 4)         = make_float4(hf0, hf1, hf2, hf3);
    *(float4*)(hl + hstep + r * 4) = make_float4(bk0, bk1, bk2, bk3);
    if (r == 0)
        g_dS[(b * PSSM_NC + c) * PSSM_DIN + d] = ds;
}

// ============================================================
// Phase B: warp-parallel carry scan (Hillis-Steele on
// (E1,h1)∘(E2,h2) = (E1E2, E2h1+h2)).  One warp per (b,dir,d,n).
// ============================================================
__global__ void __launch_bounds__(512) pssm_carry_kernel()
{
    const int wid  = (blockIdx.x * 512 + threadIdx.x) >> 5;  // 0..32767
    const int lane = threadIdx.x & 31;
    const int n    = wid & 63;
    const int d    = (wid >> 6) & 127;
    const int dir  = (wid >> 13) & 1;
    const int b    = wid >> 14;

    const int c = dir ? (31 - lane) : lane;
    const float a2n = g_a2[n];
    const int o = ((b * 2 + dir) * PSSM_NC + c) * PSSM_DIN * PSSM_NST
                + d * PSSM_NST + n;

    float h = g_hloc[o];
    float E = exp2f(a2n * g_dS[(b * PSSM_NC + c) * PSSM_DIN + d]);

    #pragma unroll
    for (int ofs = 1; ofs < 32; ofs <<= 1) {
        const float ph = __shfl_up_sync(0xffffffffu, h, ofs);
        const float pe = __shfl_up_sync(0xffffffffu, E, ofs);
        if (lane >= ofs) { h = fmaf(E, ph, h); E *= pe; }
    }
    const float ex = __shfl_up_sync(0xffffffffu, h, 1);
    g_carry[o] = (lane == 0) ? 0.f : ex;
}

// ============================================================
// Phase C body: warp = 4 d x 1 dir.  Lane (half = d-pair sel,
// r = state group) holds h[4] for d_even AND g[4] for d_odd —
// ONE B + ONE C LDS.128 per ts serves 4 d (2 wf/d/ts).
// Partials to per-warp tiles (8 x 36 each parity); flush every
// 8 ts via R14 readback (2 LDS.128 + shfl_xor(8), writers r<8).
// ============================================================
template<bool REV>
__device__ __forceinline__ void pssm_scanC_body(
    const float* __restrict__ dle, const float* __restrict__ dlo,
    const float* __restrict__ ule, const float* __restrict__ ulo,
    const float* __restrict__ Bsm, const float* __restrict__ Csm,
    float* __restrict__ tileH, float* __restrict__ tileG,
    float* __restrict__ ysum,
    const float4 a4, const float4 hce, const float4 hco,
    const int half, const int r, const int lane,
    const int ycol_e)
{
    float h0 = hce.x, h1 = hce.y, h2 = hce.z, h3 = hce.w;   // d_even
    float g0 = hco.x, g1 = hco.y, g2 = hco.z, g3 = hco.w;   // d_odd

    #pragma unroll
    for (int grp = 0; grp < 8; grp++) {
        #pragma unroll
        for (int sb = 0; sb < 2; sb++) {
            const int sidx = grp * 2 + sb;                 // 4-ts block 0..15
            const int lb = REV ? (60 - 4 * sidx) : (4 * sidx);
            const float4 de4 = __ldg((const float4*)(dle + lb));
            const float4 do4 = __ldg((const float4*)(dlo + lb));
            const float4 ue4 = __ldg((const float4*)(ule + lb));
            const float4 uo4 = __ldg((const float4*)(ulo + lb));
            const float dea[4] = {de4.x, de4.y, de4.z, de4.w};
            const float doa[4] = {do4.x, do4.y, do4.z, do4.w};
            const float uea[4] = {ue4.x, ue4.y, ue4.z, ue4.w};
            const float uoa[4] = {uo4.x, uo4.y, uo4.z, uo4.w};
            #pragma unroll
            for (int k = 0; k < 4; k++) {
                const int j = REV ? (3 - k) : k;           // compile-time
                const int l = lb + j;
                const float dje = dea[j], djo = doa[j];
                const float uje = uea[j], ujo = uoa[j];
                const float4 B4 = *(const float4*)&Bsm[l * PSSM_NST + r * 4];
                const float4 C4 = *(const float4*)&Csm[l * PSSM_NST + r * 4];
                // d_even chain + dot
                h0 = fmaf(exp2f(dje * a4.x), h0, uje * B4.x);
                h1 = fmaf(exp2f(dje * a4.y), h1, uje * B4.y);
                h2 = fmaf(exp2f(dje * a4.z), h2, uje * B4.z);
                h3 = fmaf(exp2f(dje * a4.w), h3, uje * B4.w);
                float ph = h0 * C4.x;
                ph = fmaf(h1, C4.y, ph);
                ph = fmaf(h2, C4.z, ph);
                ph = fmaf(h3, C4.w, ph);
                // d_odd chain + dot (same B4/C4!)
                g0 = fmaf(exp2f(djo * a4.x), g0, ujo * B4.x);
                g1 = fmaf(exp2f(djo * a4.y), g1, ujo * B4.y);
                g2 = fmaf(exp2f(djo * a4.z), g2, ujo * B4.z);
                g3 = fmaf(exp2f(djo * a4.w), g3, ujo * B4.w);
                float pg = g0 * C4.x;
                pg = fmaf(g1, C4.y, pg);
                pg = fmaf(g2, C4.z, pg);
                pg = fmaf(g3, C4.w, pg);
                tileH[(l & 7) * 36 + lane] = ph;           // consecutive lanes
                tileG[(l & 7) * 36 + lane] = pg;
            }
        }
        __syncwarp();
        // readback both tiles: lane (half, r) sums row (r&7),
        // col-half (r>>3) of its half; shfl_xor(8) combines.
        {
            const int row = r & 7;
            const int cb  = half * 16 + (r >> 3) * 8;
            const int lg  = REV ? (56 - 8 * grp) : (8 * grp);

            const float4 hA = *(const float4*)&tileH[row * 36 + cb + 0];
            const float4 hB = *(const float4*)&tileH[row * 36 + cb + 4];
            float ps = ((hA.x + hA.y) + (hA.z + hA.w))
                     + ((hB.x + hB.y) + (hB.z + hB.w));
            ps += __shfl_xor_sync(0xffffffffu, ps, 8);
            if (r < 8) ysum[(lg + row) * 67 + ycol_e] = ps;

            const float4 gA = *(const float4*)&tileG[row * 36 + cb + 0];
            const float4 gB = *(const float4*)&tileG[row * 36 + cb + 4];
            float qs = ((gA.x + gA.y) + (gA.z + gA.w))
                     + ((gB.x + gB.y) + (gB.z + gB.w));
            qs += __shfl_xor_sync(0xffffffffu, qs, 8);
            if (r < 8) ysum[(lg + row) * 67 + ycol_e + 2] = qs;
        }
        __syncwarp();   // protect tiles before next group's writes
    }
}

// grid 256: blk = b*128 + c*4 + dgq.  block 512 = 16 warps:
//   warp w: dir = w&1 (uniform), quad = w>>1 (4 d each);
//   half-warp = d-pair (d_even = quad*4 + half*2, d_odd = +1).
// __launch_bounds__(512, 2): 2 blocks/SM, 95KB smem each.
__global__ void __launch_bounds__(512, 2) pssm_scanC_kernel(
    float* __restrict__ y, const float* __restrict__ Dp)
{
    extern __shared__ float smC[];
    float* Bsm  = smC + SMC_B;
    float* Csm  = smC + SMC_C;
    float* tile = smC + SMC_TILE;
    float* ysum = smC + SMC_YSUM;
    float* vs   = smC + SMC_VS;

    const int blk = blockIdx.x;
    const int dgq = blk & 3;                   // 32-d group
    const int c   = (blk >> 2) & 31;
    const int b   = blk >> 7;

    const int tid  = threadIdx.x;
    const int w    = tid >> 5;
    const int lane = tid & 31;
    const int dir  = w & 1;                    // warp-uniform
    const int quad = w >> 1;                   // 0..7
    const int half = lane >> 4;
    const int r    = lane & 15;
    const int dloc_e = quad * 4 + half * 2;    // 0..30 even
    const int d_e    = dgq * 32 + dloc_e;

    {   // stage B and C: 1024 float4 each, 2+2 per thread
        const int gbase = (b * PSSM_SEQ + c * PSSM_CL) * PSSM_NST;
        const float4* sB = (const float4*)(g_B + gbase);
        const float4* sC = (const float4*)(g_C + gbase);
        float4* dB = (float4*)Bsm;
        float4* dC = (float4*)Csm;
        #pragma unroll
        for (int i = 0; i < 2; i++) {
            dB[tid + 512 * i] = __ldg(&sB[tid + 512 * i]);
            dC[tid + 512 * i] = __ldg(&sC[tid + 512 * i]);
        }
    }
    #pragma unroll
    for (int i = 0; i < 4; i++) {              // x_conv tile: 32 d x 64 l
        const int e  = tid + 512 * i;
        const int dd = e >> 6, lv = e & 63;
        vs[dd * 65 + lv] =
            g_v[(b * PSSM_DIN + dgq * 32 + dd) * PSSM_SEQ + c * PSSM_CL + lv];
    }
    __syncthreads();

    const int off_e = (b * PSSM_DIN + d_e) * PSSM_SEQ + c * PSSM_CL;
    const float* dle = g_delta + off_e;
    const float* dlo = dle + PSSM_SEQ;
    const float* ule = g_u + off_e;
    const float* ulo = ule + PSSM_SEQ;
    const float4 a4 = __ldg((const float4*)&g_a2[r * 4]);

    const float* cre = g_carry +
        ((((b * 2 + dir) * PSSM_NC + c) * PSSM_DIN + d_e) * PSSM_NST);
    const float4 hce = *(const float4*)(cre + r * 4);
    const float4 hco = *(const float4*)(cre + PSSM_NST + r * 4);

    float* tileH = tile + w * 576;             // 8 x 36
    float* tileG = tileH + 288;                // 8 x 36
    const int ycol_e = dloc_e * 2 + dir;       // odd d gets +2

    if (dir == 0)
        pssm_scanC_body<false>(dle, dlo, ule, ulo, Bsm, Csm, tileH, tileG,
                               ysum, a4, hce, hco, half, r, lane, ycol_e);
    else
        pssm_scanC_body<true >(dle, dlo, ule, ulo, Bsm, Csm, tileH, tileG,
                               ysum, a4, hce, hco, half, r, lane, ycol_e);
    __syncthreads();

    // output: 2048 cells = 64 l x 32 d, 4 per thread, coalesced stores
    #pragma unroll
    for (int i = 0; i < 4; i++) {
        const int cell = tid + 512 * i;
        const int l  = cell >> 5;
        const int dd = cell & 31;
        const int dglob = dgq * 32 + dd;
        const float val = ysum[l * 67 + dd * 2] + ysum[l * 67 + dd * 2 + 1]
                        + __ldg(&Dp[dglob]) * vs[dd * 65 + l];
        y[(size_t)(b * PSSM_SEQ + c * PSSM_CL + l) * PSSM_DIN + dglob] = val;
    }
}

// ============================================================
extern "C" void kernel_launch(void* const* d_in, const int* in_sizes, int n_in,
                              void* d_out, int out_size)
{
    const float* x  = (const float*)d_in[0];
    const float* W  = (const float*)d_in[1];
    const float* cw = (const float*)d_in[2];
    const float* cb = (const float*)d_in[3];
    const float* A  = (const float*)d_in[4];
    const float* Dp = (const float*)d_in[5];
    float* y = (float*)d_out;

    // opt-in to >48KB dynamic smem (idempotent; no allocation)
    static int smem_attr_set = 0;
    if (!smem_attr_set) {
        cudaFuncSetAttribute(pssm_scanC_kernel,
                             cudaFuncAttributeMaxDynamicSharedMemorySize,
                             SMC_TOTAL_BYTES);
        smem_attr_set = 1;
    }

    dim3 pg(64, 12);
    pssm_proj_kernel<<<pg, 256>>>(x, W, A);
    pssm_scanA_kernel<<<512, 256>>>(cw, cb);
    pssm_carry_kernel<<<2048, 512>>>();
    pssm_scanC_kernel<<<256, 512, SMC_TOTAL_BYTES>>>(y, Dp);
}